// round 1
// baseline (speedup 1.0000x reference)
#include <cuda_runtime.h>
#include <math.h>

#define NN    40000
#define EE    640000
#define FDIM  128
#define LL    3
#define NEG_SLOPE 0.2f
#define BN_EPS 1e-5f

// ---------------- scratch (device globals; no allocation allowed) ----------------
__device__ int g_deg[NN];
__device__ int g_rowstart[NN];
__device__ int g_cursor[NN];
__device__ int g_csrc[EE];
__device__ __align__(16) float g_h[(size_t)NN * FDIM];     // 20.5 MB
__device__ __align__(16) float g_att[(size_t)NN * 8];      // a_src[4], a_dst[4] per node
__device__ __align__(16) float g_xa[(size_t)NN * FDIM];    // ping
__device__ __align__(16) float g_xb[(size_t)NN * FDIM];    // pong

// ---------------- CSR build ----------------
__global__ void k_zero_deg() {
    int i = blockIdx.x * blockDim.x + threadIdx.x;
    if (i < NN) g_deg[i] = 0;
}

__global__ void k_count(const int* __restrict__ ei) {
    int e = blockIdx.x * blockDim.x + threadIdx.x;
    if (e < EE) atomicAdd(&g_deg[ei[EE + e]], 1);
}

// Single-block scan over 40000 degrees: warp shfl scan + cross-warp scan.
__global__ void k_scan() {
    __shared__ int swsum[32];
    __shared__ int carry;
    int tid = threadIdx.x, lane = tid & 31, wid = tid >> 5;
    if (tid == 0) carry = 0;
    __syncthreads();
    for (int base = 0; base < NN; base += 1024) {
        int i = base + tid;
        int v = (i < NN) ? g_deg[i] : 0;
        int incl = v;
        #pragma unroll
        for (int o = 1; o < 32; o <<= 1) {
            int t = __shfl_up_sync(0xffffffffu, incl, o);
            if (lane >= o) incl += t;
        }
        if (lane == 31) swsum[wid] = incl;
        __syncthreads();
        if (wid == 0) {
            int u = swsum[lane];
            int ui = u;
            #pragma unroll
            for (int o = 1; o < 32; o <<= 1) {
                int t = __shfl_up_sync(0xffffffffu, ui, o);
                if (lane >= o) ui += t;
            }
            swsum[lane] = ui - u;   // exclusive warp offsets
        }
        __syncthreads();
        int excl = carry + swsum[wid] + incl - v;
        if (i < NN) { g_rowstart[i] = excl; g_cursor[i] = excl; }
        __syncthreads();            // everyone done reading carry/swsum
        if (tid == 1023) carry = excl + v;   // = carry_old + tile total
        __syncthreads();
    }
}

__global__ void k_scatter(const int* __restrict__ ei) {
    int e = blockIdx.x * blockDim.x + threadIdx.x;
    if (e < EE) {
        int d = ei[EE + e];
        int p = atomicAdd(&g_cursor[d], 1);
        g_csrc[p] = ei[e];
    }
}

// ---------------- GEMM: h = x @ W, fused a_src / a_dst dot products ----------------
// Warp per row. Lane owns output channels [4*lane, 4*lane+3].
// W (64KB) is L1-resident; x row broadcast via shfl.
__global__ void __launch_bounds__(256) k_gemm(
    const float* __restrict__ x, const float* __restrict__ Wm,
    const float* __restrict__ asrc, const float* __restrict__ adst)
{
    int lane = threadIdx.x & 31, wid = threadIdx.x >> 5;
    int nwarps = (blockDim.x >> 5) * gridDim.x;
    for (int row = blockIdx.x * (blockDim.x >> 5) + wid; row < NN; row += nwarps) {
        float4 xr = *(const float4*)(x + (size_t)row * FDIM + lane * 4);
        float4 acc = make_float4(0.f, 0.f, 0.f, 0.f);
        #pragma unroll 4
        for (int k4 = 0; k4 < 32; k4++) {
            float bx = __shfl_sync(0xffffffffu, xr.x, k4);
            float by = __shfl_sync(0xffffffffu, xr.y, k4);
            float bz = __shfl_sync(0xffffffffu, xr.z, k4);
            float bw = __shfl_sync(0xffffffffu, xr.w, k4);
            const float* wp = Wm + (k4 * 4) * FDIM + lane * 4;
            float4 w0 = __ldg((const float4*)wp);
            float4 w1 = __ldg((const float4*)(wp + FDIM));
            float4 w2 = __ldg((const float4*)(wp + 2 * FDIM));
            float4 w3 = __ldg((const float4*)(wp + 3 * FDIM));
            acc.x = fmaf(bx, w0.x, acc.x); acc.y = fmaf(bx, w0.y, acc.y);
            acc.z = fmaf(bx, w0.z, acc.z); acc.w = fmaf(bx, w0.w, acc.w);
            acc.x = fmaf(by, w1.x, acc.x); acc.y = fmaf(by, w1.y, acc.y);
            acc.z = fmaf(by, w1.z, acc.z); acc.w = fmaf(by, w1.w, acc.w);
            acc.x = fmaf(bz, w2.x, acc.x); acc.y = fmaf(bz, w2.y, acc.y);
            acc.z = fmaf(bz, w2.z, acc.z); acc.w = fmaf(bz, w2.w, acc.w);
            acc.x = fmaf(bw, w3.x, acc.x); acc.y = fmaf(bw, w3.y, acc.y);
            acc.z = fmaf(bw, w3.z, acc.z); acc.w = fmaf(bw, w3.w, acc.w);
        }
        *(float4*)(g_h + (size_t)row * FDIM + lane * 4) = acc;

        // fused attention coefficients: a_s[n,h] = sum_c h[n,h,c]*att_src[h,c]
        float4 s4 = __ldg((const float4*)(asrc + lane * 4));
        float4 d4 = __ldg((const float4*)(adst + lane * 4));
        float sa = acc.x * s4.x + acc.y * s4.y + acc.z * s4.z + acc.w * s4.w;
        float sd = acc.x * d4.x + acc.y * d4.y + acc.z * d4.z + acc.w * d4.w;
        // reduce within 8-lane group (one head = 32 channels = 8 lanes)
        sa += __shfl_xor_sync(0xffffffffu, sa, 4);
        sa += __shfl_xor_sync(0xffffffffu, sa, 2);
        sa += __shfl_xor_sync(0xffffffffu, sa, 1);
        sd += __shfl_xor_sync(0xffffffffu, sd, 4);
        sd += __shfl_xor_sync(0xffffffffu, sd, 2);
        sd += __shfl_xor_sync(0xffffffffu, sd, 1);
        if ((lane & 7) == 0) {
            int hh = lane >> 3;
            g_att[(size_t)row * 8 + hh]     = sa;
            g_att[(size_t)row * 8 + 4 + hh] = sd;
        }
    }
}

// ---------------- Aggregate: atomic-free, warp per destination ----------------
// Two passes over in-edges (+ implicit self-loop):
//   pass 1: per-head max of leaky_relu(a_s[src]+a_d[dst])
//   pass 2: w = exp(e-max); accumulate denom and sum(w * h[src]); epilogue does
//           /denom + bias + BN + ReLU (all fused).
__global__ void __launch_bounds__(256) k_aggregate(
    const float* __restrict__ bias_, const float* __restrict__ gamma_,
    const float* __restrict__ beta_, const float* __restrict__ mean_,
    const float* __restrict__ var_,  float* __restrict__ xout)
{
    __shared__ int    ssrc[8][32];
    __shared__ float4 sw4[8][32];
    int lane = threadIdx.x & 31, wid = threadIdx.x >> 5;
    int dst = blockIdx.x * 8 + wid;
    if (dst >= NN) return;

    int start = g_rowstart[dst];
    int d     = g_deg[dst];
    int total = d + 1;   // + self-loop
    float4 ad4 = *(const float4*)(g_att + (size_t)dst * 8 + 4);

    // ---- pass 1: per-head max ----
    float m0 = -1e30f, m1 = -1e30f, m2 = -1e30f, m3 = -1e30f;
    for (int i = lane; i < total; i += 32) {
        int src = (i < d) ? g_csrc[start + i] : dst;
        float4 as4 = *(const float4*)(g_att + (size_t)src * 8);
        float e0 = as4.x + ad4.x; e0 = (e0 > 0.f) ? e0 : NEG_SLOPE * e0;
        float e1 = as4.y + ad4.y; e1 = (e1 > 0.f) ? e1 : NEG_SLOPE * e1;
        float e2 = as4.z + ad4.z; e2 = (e2 > 0.f) ? e2 : NEG_SLOPE * e2;
        float e3 = as4.w + ad4.w; e3 = (e3 > 0.f) ? e3 : NEG_SLOPE * e3;
        m0 = fmaxf(m0, e0); m1 = fmaxf(m1, e1); m2 = fmaxf(m2, e2); m3 = fmaxf(m3, e3);
    }
    #pragma unroll
    for (int o = 16; o; o >>= 1) {
        m0 = fmaxf(m0, __shfl_xor_sync(0xffffffffu, m0, o));
        m1 = fmaxf(m1, __shfl_xor_sync(0xffffffffu, m1, o));
        m2 = fmaxf(m2, __shfl_xor_sync(0xffffffffu, m2, o));
        m3 = fmaxf(m3, __shfl_xor_sync(0xffffffffu, m3, o));
    }

    // ---- pass 2: weighted accumulation ----
    int hl = lane >> 3;                       // this lane's head (channels 4*lane..+3)
    float4 acc = make_float4(0.f, 0.f, 0.f, 0.f);
    float dn0 = 0.f, dn1 = 0.f, dn2 = 0.f, dn3 = 0.f;

    for (int base = 0; base < total; base += 32) {
        int idx = base + lane;
        int cnt = min(32, total - base);
        if (idx < total) {
            int src = (idx < d) ? g_csrc[start + idx] : dst;
            float4 as4 = *(const float4*)(g_att + (size_t)src * 8);
            float e0 = as4.x + ad4.x; e0 = (e0 > 0.f) ? e0 : NEG_SLOPE * e0;
            float e1 = as4.y + ad4.y; e1 = (e1 > 0.f) ? e1 : NEG_SLOPE * e1;
            float e2 = as4.z + ad4.z; e2 = (e2 > 0.f) ? e2 : NEG_SLOPE * e2;
            float e3 = as4.w + ad4.w; e3 = (e3 > 0.f) ? e3 : NEG_SLOPE * e3;
            float w0 = __expf(e0 - m0), w1 = __expf(e1 - m1);
            float w2 = __expf(e2 - m2), w3 = __expf(e3 - m3);
            dn0 += w0; dn1 += w1; dn2 += w2; dn3 += w3;
            ssrc[wid][lane] = src;
            sw4[wid][lane]  = make_float4(w0, w1, w2, w3);
        }
        __syncwarp();
        for (int j = 0; j < cnt; j++) {
            int   sj = ssrc[wid][j];
            float wj = ((const float*)&sw4[wid][j])[hl];
            float4 hv = *(const float4*)(g_h + (size_t)sj * FDIM + lane * 4);
            acc.x = fmaf(wj, hv.x, acc.x);
            acc.y = fmaf(wj, hv.y, acc.y);
            acc.z = fmaf(wj, hv.z, acc.z);
            acc.w = fmaf(wj, hv.w, acc.w);
        }
        __syncwarp();
    }

    #pragma unroll
    for (int o = 16; o; o >>= 1) {
        dn0 += __shfl_xor_sync(0xffffffffu, dn0, o);
        dn1 += __shfl_xor_sync(0xffffffffu, dn1, o);
        dn2 += __shfl_xor_sync(0xffffffffu, dn2, o);
        dn3 += __shfl_xor_sync(0xffffffffu, dn3, o);
    }
    float dsel = (hl == 0) ? dn0 : (hl == 1) ? dn1 : (hl == 2) ? dn2 : dn3;
    float inv = 1.0f / (dsel + 1e-16f);

    int c0 = lane * 4;
    float4 b  = __ldg((const float4*)(bias_  + c0));
    float4 mu = __ldg((const float4*)(mean_  + c0));
    float4 va = __ldg((const float4*)(var_   + c0));
    float4 ga = __ldg((const float4*)(gamma_ + c0));
    float4 be = __ldg((const float4*)(beta_  + c0));
    float4 o4;
    o4.x = fmaxf(0.f, (acc.x * inv + b.x - mu.x) * rsqrtf(va.x + BN_EPS) * ga.x + be.x);
    o4.y = fmaxf(0.f, (acc.y * inv + b.y - mu.y) * rsqrtf(va.y + BN_EPS) * ga.y + be.y);
    o4.z = fmaxf(0.f, (acc.z * inv + b.z - mu.z) * rsqrtf(va.z + BN_EPS) * ga.z + be.z);
    o4.w = fmaxf(0.f, (acc.w * inv + b.w - mu.w) * rsqrtf(va.w + BN_EPS) * ga.w + be.w);
    *(float4*)(xout + (size_t)dst * FDIM + c0) = o4;
}

// ---------------- final projection: out[n] = x[n] . w_out + b_out ----------------
__global__ void __launch_bounds__(256) k_final(
    const float* __restrict__ x, const float* __restrict__ wout,
    const float* __restrict__ bout, float* __restrict__ out)
{
    int lane = threadIdx.x & 31, wid = threadIdx.x >> 5;
    int n = blockIdx.x * 8 + wid;
    if (n >= NN) return;
    float4 xv = *(const float4*)(x + (size_t)n * FDIM + lane * 4);
    float4 wv = __ldg((const float4*)(wout + lane * 4));
    float s = xv.x * wv.x + xv.y * wv.y + xv.z * wv.z + xv.w * wv.w;
    #pragma unroll
    for (int o = 16; o; o >>= 1) s += __shfl_xor_sync(0xffffffffu, s, o);
    if (lane == 0) out[n] = s + bout[0];
}

// ---------------- launch ----------------
extern "C" void kernel_launch(void* const* d_in, const int* in_sizes, int n_in,
                              void* d_out, int out_size)
{
    const float* x     = (const float*)d_in[0];
    const int*   ei    = (const int*)  d_in[1];
    const float* W     = (const float*)d_in[2];
    const float* asrc  = (const float*)d_in[3];
    const float* adst  = (const float*)d_in[4];
    const float* bias  = (const float*)d_in[5];
    const float* gamma = (const float*)d_in[6];
    const float* beta  = (const float*)d_in[7];
    const float* mean  = (const float*)d_in[8];
    const float* var   = (const float*)d_in[9];
    const float* wout  = (const float*)d_in[10];
    const float* bout  = (const float*)d_in[11];

    float *pxa = 0, *pxb = 0;
    cudaGetSymbolAddress((void**)&pxa, g_xa);
    cudaGetSymbolAddress((void**)&pxb, g_xb);

    // CSR build (edge_index is layer-invariant)
    k_zero_deg<<<(NN + 255) / 256, 256>>>();
    k_count<<<(EE + 255) / 256, 256>>>(ei);
    k_scan<<<1, 1024>>>();
    k_scatter<<<(EE + 255) / 256, 256>>>(ei);

    const float* xin = x;
    float* bufs[2] = {pxa, pxb};
    for (int l = 0; l < LL; l++) {
        k_gemm<<<592, 256>>>(xin, W + (size_t)l * FDIM * FDIM,
                             asrc + l * FDIM, adst + l * FDIM);
        float* xo = bufs[l & 1];
        k_aggregate<<<NN / 8, 256>>>(bias + l * FDIM, gamma + l * FDIM,
                                     beta + l * FDIM, mean + l * FDIM,
                                     var + l * FDIM, xo);
        xin = xo;
    }
    k_final<<<NN / 8, 256>>>(xin, wout, bout, (float*)d_out);
}

// round 2
// speedup vs baseline: 1.4152x; 1.4152x over previous
#include <cuda_runtime.h>
#include <math.h>

#define NN    40000
#define EE    640000
#define FDIM  128
#define LL    3
#define NEG_SLOPE 0.2f
#define BN_EPS 1e-5f

// ---------------- scratch (device globals; no allocation allowed) ----------------
__device__ int g_deg[NN];
__device__ int g_rowstart[NN];
__device__ int g_cursor[NN];
__device__ int g_csrc[EE];
__device__ __align__(16) float g_h[(size_t)NN * FDIM];     // 20.5 MB
__device__ __align__(16) float g_att[(size_t)NN * 8];      // a_src[4], a_dst[4] per node
__device__ __align__(16) float g_xa[(size_t)NN * FDIM];    // ping
__device__ __align__(16) float g_xb[(size_t)NN * FDIM];    // pong

// ---------------- CSR build ----------------
__global__ void k_zero_deg() {
    int i = blockIdx.x * blockDim.x + threadIdx.x;
    if (i < NN) g_deg[i] = 0;
}

// 4 edges per thread, vectorized loads (previous version was latency-bound at issue=3.5%)
__global__ void k_count4(const int* __restrict__ ei) {
    int t = blockIdx.x * blockDim.x + threadIdx.x;
    if (t < EE / 4) {
        int4 d4 = __ldg((const int4*)(ei + EE) + t);
        atomicAdd(&g_deg[d4.x], 1);
        atomicAdd(&g_deg[d4.y], 1);
        atomicAdd(&g_deg[d4.z], 1);
        atomicAdd(&g_deg[d4.w], 1);
    }
}

// Single-block scan over 40000 degrees: warp shfl scan + cross-warp scan.
__global__ void k_scan() {
    __shared__ int swsum[32];
    __shared__ int carry;
    int tid = threadIdx.x, lane = tid & 31, wid = tid >> 5;
    if (tid == 0) carry = 0;
    __syncthreads();
    for (int base = 0; base < NN; base += 1024) {
        int i = base + tid;
        int v = (i < NN) ? g_deg[i] : 0;
        int incl = v;
        #pragma unroll
        for (int o = 1; o < 32; o <<= 1) {
            int t = __shfl_up_sync(0xffffffffu, incl, o);
            if (lane >= o) incl += t;
        }
        if (lane == 31) swsum[wid] = incl;
        __syncthreads();
        if (wid == 0) {
            int u = swsum[lane];
            int ui = u;
            #pragma unroll
            for (int o = 1; o < 32; o <<= 1) {
                int t = __shfl_up_sync(0xffffffffu, ui, o);
                if (lane >= o) ui += t;
            }
            swsum[lane] = ui - u;   // exclusive warp offsets
        }
        __syncthreads();
        int excl = carry + swsum[wid] + incl - v;
        if (i < NN) { g_rowstart[i] = excl; g_cursor[i] = excl; }
        __syncthreads();
        if (tid == 1023) carry = excl + v;
        __syncthreads();
    }
}

__global__ void k_scatter4(const int* __restrict__ ei) {
    int t = blockIdx.x * blockDim.x + threadIdx.x;
    if (t < EE / 4) {
        int4 s4 = __ldg((const int4*)ei + t);
        int4 d4 = __ldg((const int4*)(ei + EE) + t);
        g_csrc[atomicAdd(&g_cursor[d4.x], 1)] = s4.x;
        g_csrc[atomicAdd(&g_cursor[d4.y], 1)] = s4.y;
        g_csrc[atomicAdd(&g_cursor[d4.z], 1)] = s4.z;
        g_csrc[atomicAdd(&g_cursor[d4.w], 1)] = s4.w;
    }
}

// ---------------- GEMM: h = x @ W, fused a_src / a_dst dot products ----------------
// Warp handles 4 consecutive rows: W loads amortized 4x, x read via uniform
// L1-resident LDG (replaces 128 SHFL/row with 32 uniform LDG/row).
// Lane owns output channels [4*lane, 4*lane+3] of each row.
__global__ void __launch_bounds__(256) k_gemm(
    const float* __restrict__ x, const float* __restrict__ Wm,
    const float* __restrict__ asrc, const float* __restrict__ adst)
{
    int lane = threadIdx.x & 31, wid = threadIdx.x >> 5;
    int row0 = (blockIdx.x * 8 + wid) * 4;
    if (row0 >= NN) return;
    const float* xp0 = x + (size_t)row0 * FDIM;
    const float* xp1 = xp0 + FDIM;
    const float* xp2 = xp1 + FDIM;
    const float* xp3 = xp2 + FDIM;
    const float* wp  = Wm + lane * 4;

    float4 acc0 = make_float4(0.f,0.f,0.f,0.f), acc1 = acc0, acc2 = acc0, acc3 = acc0;

    #pragma unroll 4
    for (int k4 = 0; k4 < 32; k4++) {
        float4 w0 = __ldg((const float4*)(wp + (k4 * 4 + 0) * FDIM));
        float4 w1 = __ldg((const float4*)(wp + (k4 * 4 + 1) * FDIM));
        float4 w2 = __ldg((const float4*)(wp + (k4 * 4 + 2) * FDIM));
        float4 w3 = __ldg((const float4*)(wp + (k4 * 4 + 3) * FDIM));
        float4 xv0 = __ldg((const float4*)(xp0 + k4 * 4));
        float4 xv1 = __ldg((const float4*)(xp1 + k4 * 4));
        float4 xv2 = __ldg((const float4*)(xp2 + k4 * 4));
        float4 xv3 = __ldg((const float4*)(xp3 + k4 * 4));

        acc0.x = fmaf(xv0.x, w0.x, acc0.x); acc0.y = fmaf(xv0.x, w0.y, acc0.y);
        acc0.z = fmaf(xv0.x, w0.z, acc0.z); acc0.w = fmaf(xv0.x, w0.w, acc0.w);
        acc0.x = fmaf(xv0.y, w1.x, acc0.x); acc0.y = fmaf(xv0.y, w1.y, acc0.y);
        acc0.z = fmaf(xv0.y, w1.z, acc0.z); acc0.w = fmaf(xv0.y, w1.w, acc0.w);
        acc0.x = fmaf(xv0.z, w2.x, acc0.x); acc0.y = fmaf(xv0.z, w2.y, acc0.y);
        acc0.z = fmaf(xv0.z, w2.z, acc0.z); acc0.w = fmaf(xv0.z, w2.w, acc0.w);
        acc0.x = fmaf(xv0.w, w3.x, acc0.x); acc0.y = fmaf(xv0.w, w3.y, acc0.y);
        acc0.z = fmaf(xv0.w, w3.z, acc0.z); acc0.w = fmaf(xv0.w, w3.w, acc0.w);

        acc1.x = fmaf(xv1.x, w0.x, acc1.x); acc1.y = fmaf(xv1.x, w0.y, acc1.y);
        acc1.z = fmaf(xv1.x, w0.z, acc1.z); acc1.w = fmaf(xv1.x, w0.w, acc1.w);
        acc1.x = fmaf(xv1.y, w1.x, acc1.x); acc1.y = fmaf(xv1.y, w1.y, acc1.y);
        acc1.z = fmaf(xv1.y, w1.z, acc1.z); acc1.w = fmaf(xv1.y, w1.w, acc1.w);
        acc1.x = fmaf(xv1.z, w2.x, acc1.x); acc1.y = fmaf(xv1.z, w2.y, acc1.y);
        acc1.z = fmaf(xv1.z, w2.z, acc1.z); acc1.w = fmaf(xv1.z, w2.w, acc1.w);
        acc1.x = fmaf(xv1.w, w3.x, acc1.x); acc1.y = fmaf(xv1.w, w3.y, acc1.y);
        acc1.z = fmaf(xv1.w, w3.z, acc1.z); acc1.w = fmaf(xv1.w, w3.w, acc1.w);

        acc2.x = fmaf(xv2.x, w0.x, acc2.x); acc2.y = fmaf(xv2.x, w0.y, acc2.y);
        acc2.z = fmaf(xv2.x, w0.z, acc2.z); acc2.w = fmaf(xv2.x, w0.w, acc2.w);
        acc2.x = fmaf(xv2.y, w1.x, acc2.x); acc2.y = fmaf(xv2.y, w1.y, acc2.y);
        acc2.z = fmaf(xv2.y, w1.z, acc2.z); acc2.w = fmaf(xv2.y, w1.w, acc2.w);
        acc2.x = fmaf(xv2.z, w2.x, acc2.x); acc2.y = fmaf(xv2.z, w2.y, acc2.y);
        acc2.z = fmaf(xv2.z, w2.z, acc2.z); acc2.w = fmaf(xv2.z, w2.w, acc2.w);
        acc2.x = fmaf(xv2.w, w3.x, acc2.x); acc2.y = fmaf(xv2.w, w3.y, acc2.y);
        acc2.z = fmaf(xv2.w, w3.z, acc2.z); acc2.w = fmaf(xv2.w, w3.w, acc2.w);

        acc3.x = fmaf(xv3.x, w0.x, acc3.x); acc3.y = fmaf(xv3.x, w0.y, acc3.y);
        acc3.z = fmaf(xv3.x, w0.z, acc3.z); acc3.w = fmaf(xv3.x, w0.w, acc3.w);
        acc3.x = fmaf(xv3.y, w1.x, acc3.x); acc3.y = fmaf(xv3.y, w1.y, acc3.y);
        acc3.z = fmaf(xv3.y, w1.z, acc3.z); acc3.w = fmaf(xv3.y, w1.w, acc3.w);
        acc3.x = fmaf(xv3.z, w2.x, acc3.x); acc3.y = fmaf(xv3.z, w2.y, acc3.y);
        acc3.z = fmaf(xv3.z, w2.z, acc3.z); acc3.w = fmaf(xv3.z, w2.w, acc3.w);
        acc3.x = fmaf(xv3.w, w3.x, acc3.x); acc3.y = fmaf(xv3.w, w3.y, acc3.y);
        acc3.z = fmaf(xv3.w, w3.z, acc3.z); acc3.w = fmaf(xv3.w, w3.w, acc3.w);
    }

    float4 s4 = __ldg((const float4*)(asrc + lane * 4));
    float4 d4 = __ldg((const float4*)(adst + lane * 4));

    #pragma unroll
    for (int r = 0; r < 4; r++) {
        float4 acc = (r == 0) ? acc0 : (r == 1) ? acc1 : (r == 2) ? acc2 : acc3;
        int row = row0 + r;
        *(float4*)(g_h + (size_t)row * FDIM + lane * 4) = acc;
        float sa = acc.x * s4.x + acc.y * s4.y + acc.z * s4.z + acc.w * s4.w;
        float sd = acc.x * d4.x + acc.y * d4.y + acc.z * d4.z + acc.w * d4.w;
        sa += __shfl_xor_sync(0xffffffffu, sa, 4);
        sa += __shfl_xor_sync(0xffffffffu, sa, 2);
        sa += __shfl_xor_sync(0xffffffffu, sa, 1);
        sd += __shfl_xor_sync(0xffffffffu, sd, 4);
        sd += __shfl_xor_sync(0xffffffffu, sd, 2);
        sd += __shfl_xor_sync(0xffffffffu, sd, 1);
        if ((lane & 7) == 0) {
            int hh = lane >> 3;
            g_att[(size_t)row * 8 + hh]     = sa;
            g_att[(size_t)row * 8 + 4 + hh] = sd;
        }
    }
}

// ---------------- Aggregate: single pass, atomic-free, warp per destination ----------------
// No max-subtraction: alpha = exp(e)/sum(exp(e)) is mathematically identical to
// the max-shifted form; |e| here is O(1) so exp cannot overflow.
// FINAL=true fuses the x@w_out projection (removes k_final + layer-3 x traffic).
template<bool FINAL>
__global__ void __launch_bounds__(256) k_aggregate(
    const float* __restrict__ bias_, const float* __restrict__ gamma_,
    const float* __restrict__ beta_, const float* __restrict__ mean_,
    const float* __restrict__ var_,  float* __restrict__ xout,
    const float* __restrict__ wout,  const float* __restrict__ bout)
{
    __shared__ int    ssrc[8][32];
    __shared__ float4 sw4[8][32];
    int lane = threadIdx.x & 31, wid = threadIdx.x >> 5;
    int dst = blockIdx.x * 8 + wid;
    if (dst >= NN) return;

    int start = g_rowstart[dst];
    int d     = g_deg[dst];
    int total = d + 1;   // + self-loop
    float4 ad4 = *(const float4*)(g_att + (size_t)dst * 8 + 4);

    int hl = lane >> 3;                       // this lane's head
    float4 acc = make_float4(0.f, 0.f, 0.f, 0.f);
    float dn0 = 0.f, dn1 = 0.f, dn2 = 0.f, dn3 = 0.f;
    const float* hbase = g_h + (size_t)lane * 4;

    for (int base = 0; base < total; base += 32) {
        int idx = base + lane;
        int cnt = min(32, total - base);
        if (idx < total) {
            int src = (idx < d) ? __ldg(&g_csrc[start + idx]) : dst;
            float4 as4 = __ldg((const float4*)(g_att + (size_t)src * 8));
            float e0 = as4.x + ad4.x; e0 = (e0 > 0.f) ? e0 : NEG_SLOPE * e0;
            float e1 = as4.y + ad4.y; e1 = (e1 > 0.f) ? e1 : NEG_SLOPE * e1;
            float e2 = as4.z + ad4.z; e2 = (e2 > 0.f) ? e2 : NEG_SLOPE * e2;
            float e3 = as4.w + ad4.w; e3 = (e3 > 0.f) ? e3 : NEG_SLOPE * e3;
            float w0 = __expf(e0), w1 = __expf(e1);
            float w2 = __expf(e2), w3 = __expf(e3);
            dn0 += w0; dn1 += w1; dn2 += w2; dn3 += w3;
            ssrc[wid][lane] = src;
            sw4[wid][lane]  = make_float4(w0, w1, w2, w3);
        }
        __syncwarp();
        int j = 0;
        for (; j + 4 <= cnt; j += 4) {     // MLP=4 gather
            int s0 = ssrc[wid][j],     s1 = ssrc[wid][j + 1];
            int s2 = ssrc[wid][j + 2], s3 = ssrc[wid][j + 3];
            float wj0 = ((const float*)&sw4[wid][j    ])[hl];
            float wj1 = ((const float*)&sw4[wid][j + 1])[hl];
            float wj2 = ((const float*)&sw4[wid][j + 2])[hl];
            float wj3 = ((const float*)&sw4[wid][j + 3])[hl];
            float4 h0 = __ldg((const float4*)(hbase + (size_t)s0 * FDIM));
            float4 h1 = __ldg((const float4*)(hbase + (size_t)s1 * FDIM));
            float4 h2 = __ldg((const float4*)(hbase + (size_t)s2 * FDIM));
            float4 h3 = __ldg((const float4*)(hbase + (size_t)s3 * FDIM));
            acc.x = fmaf(wj0, h0.x, acc.x); acc.y = fmaf(wj0, h0.y, acc.y);
            acc.z = fmaf(wj0, h0.z, acc.z); acc.w = fmaf(wj0, h0.w, acc.w);
            acc.x = fmaf(wj1, h1.x, acc.x); acc.y = fmaf(wj1, h1.y, acc.y);
            acc.z = fmaf(wj1, h1.z, acc.z); acc.w = fmaf(wj1, h1.w, acc.w);
            acc.x = fmaf(wj2, h2.x, acc.x); acc.y = fmaf(wj2, h2.y, acc.y);
            acc.z = fmaf(wj2, h2.z, acc.z); acc.w = fmaf(wj2, h2.w, acc.w);
            acc.x = fmaf(wj3, h3.x, acc.x); acc.y = fmaf(wj3, h3.y, acc.y);
            acc.z = fmaf(wj3, h3.z, acc.z); acc.w = fmaf(wj3, h3.w, acc.w);
        }
        for (; j < cnt; j++) {
            int   sj = ssrc[wid][j];
            float wj = ((const float*)&sw4[wid][j])[hl];
            float4 hv = __ldg((const float4*)(hbase + (size_t)sj * FDIM));
            acc.x = fmaf(wj, hv.x, acc.x);
            acc.y = fmaf(wj, hv.y, acc.y);
            acc.z = fmaf(wj, hv.z, acc.z);
            acc.w = fmaf(wj, hv.w, acc.w);
        }
        __syncwarp();
    }

    #pragma unroll
    for (int o = 16; o; o >>= 1) {
        dn0 += __shfl_xor_sync(0xffffffffu, dn0, o);
        dn1 += __shfl_xor_sync(0xffffffffu, dn1, o);
        dn2 += __shfl_xor_sync(0xffffffffu, dn2, o);
        dn3 += __shfl_xor_sync(0xffffffffu, dn3, o);
    }
    float dsel = (hl == 0) ? dn0 : (hl == 1) ? dn1 : (hl == 2) ? dn2 : dn3;
    float inv = 1.0f / (dsel + 1e-16f);

    int c0 = lane * 4;
    float4 b  = __ldg((const float4*)(bias_  + c0));
    float4 mu = __ldg((const float4*)(mean_  + c0));
    float4 va = __ldg((const float4*)(var_   + c0));
    float4 ga = __ldg((const float4*)(gamma_ + c0));
    float4 be = __ldg((const float4*)(beta_  + c0));
    float4 o4;
    o4.x = fmaxf(0.f, (acc.x * inv + b.x - mu.x) * rsqrtf(va.x + BN_EPS) * ga.x + be.x);
    o4.y = fmaxf(0.f, (acc.y * inv + b.y - mu.y) * rsqrtf(va.y + BN_EPS) * ga.y + be.y);
    o4.z = fmaxf(0.f, (acc.z * inv + b.z - mu.z) * rsqrtf(va.z + BN_EPS) * ga.z + be.z);
    o4.w = fmaxf(0.f, (acc.w * inv + b.w - mu.w) * rsqrtf(va.w + BN_EPS) * ga.w + be.w);

    if (FINAL) {
        float4 wv = __ldg((const float4*)(wout + c0));
        float s = o4.x * wv.x + o4.y * wv.y + o4.z * wv.z + o4.w * wv.w;
        #pragma unroll
        for (int o = 16; o; o >>= 1) s += __shfl_xor_sync(0xffffffffu, s, o);
        if (lane == 0) xout[dst] = s + __ldg(bout);
    } else {
        *(float4*)(xout + (size_t)dst * FDIM + c0) = o4;
    }
}

// ---------------- launch ----------------
extern "C" void kernel_launch(void* const* d_in, const int* in_sizes, int n_in,
                              void* d_out, int out_size)
{
    const float* x     = (const float*)d_in[0];
    const int*   ei    = (const int*)  d_in[1];
    const float* W     = (const float*)d_in[2];
    const float* asrc  = (const float*)d_in[3];
    const float* adst  = (const float*)d_in[4];
    const float* bias  = (const float*)d_in[5];
    const float* gamma = (const float*)d_in[6];
    const float* beta  = (const float*)d_in[7];
    const float* mean  = (const float*)d_in[8];
    const float* var   = (const float*)d_in[9];
    const float* wout  = (const float*)d_in[10];
    const float* bout  = (const float*)d_in[11];

    float *pxa = 0, *pxb = 0;
    cudaGetSymbolAddress((void**)&pxa, g_xa);
    cudaGetSymbolAddress((void**)&pxb, g_xb);

    // CSR build (edge_index is layer-invariant)
    k_zero_deg<<<(NN + 255) / 256, 256>>>();
    k_count4<<<(EE / 4 + 255) / 256, 256>>>(ei);
    k_scan<<<1, 1024>>>();
    k_scatter4<<<(EE / 4 + 255) / 256, 256>>>(ei);

    const float* xin = x;
    float* bufs[2] = {pxa, pxb};
    for (int l = 0; l < LL; l++) {
        k_gemm<<<1250, 256>>>(xin, W + (size_t)l * FDIM * FDIM,
                              asrc + l * FDIM, adst + l * FDIM);
        if (l < LL - 1) {
            float* xo = bufs[l & 1];
            k_aggregate<false><<<NN / 8, 256>>>(bias + l * FDIM, gamma + l * FDIM,
                                                beta + l * FDIM, mean + l * FDIM,
                                                var + l * FDIM, xo, wout, bout);
            xin = xo;
        } else {
            k_aggregate<true><<<NN / 8, 256>>>(bias + l * FDIM, gamma + l * FDIM,
                                               beta + l * FDIM, mean + l * FDIM,
                                               var + l * FDIM, (float*)d_out, wout, bout);
        }
    }
}